// round 13
// baseline (speedup 1.0000x reference)
#include <cuda_runtime.h>
#include <cstdint>

#define HWDIM 1024
#define NPIX  (HWDIM*HWDIM)
#define NSEG  5000
#define R1    1449
#define NR1   (R1*R1)
#define CROP  211
#define CB    25
#define TB    10
#define OUT_TOTAL 1600000

#define C45f 0.70710678118654752440f

// -------- device scratch (static; no runtime allocation) --------
__device__ float    v12_rotimg[3*NR1];      // +45-rotated image, 1449^2 per channel
__device__ float2   v12_gbase[3*NPIX];      // Scharr of original img, (G0,G1) per c
__device__ float2   v12_grot[3*NPIX];       // Scharr(rotimg) sampled through -45 rot + crop
__device__ unsigned v12_mink[12], v12_maxk[12];
__device__ float    v12_nmin[24], v12_nrcp[24];  // hmin, frcp_rn(hmax-hmin) per deriv channel
__device__ int      v12_tbin[24];           // bin of value 0.0 per deriv channel
__device__ int4     v12_bbox[NSEG];         // {xmin, xmax, ymin, ymax}
__device__ int      v12_sz[NSEG];
__device__ int      v12_ch[NSEG*3*CB];
// texture hist: [s][c][pair(4)][bin(10)] 32-bit words; low 16 = even channel, high 16 = odd.
__device__ unsigned v12_th[NSEG*3*4*TB];
__device__ int      v12_w64;

// -------- helpers --------
__device__ __forceinline__ unsigned fkey(float f){
    unsigned u = __float_as_uint(f);
    return (u & 0x80000000u) ? ~u : (u | 0x80000000u);
}
__device__ __forceinline__ float unfkey(unsigned k){
    unsigned u = (k & 0x80000000u) ? (k ^ 0x80000000u) : ~k;
    return __uint_as_float(u);
}
// XLA-exact binning: deriv = (val - hmin) * rcp ; qt = trunc(deriv * 9), clamped.
__device__ __forceinline__ int binq(float val, float hmin, float rcp){
    float d = __fmul_rn(__fsub_rn(val, hmin), rcp);
    int q = (int)__fmul_rn(d, 9.0f);
    return min(max(q, 0), TB-1);
}

// Scharr per reference (lax.conv = cross-correlation, zero pad):
// k0 = [[-3,0,3],[10,0,10],[-3,0,3]], k1 = k0^T.
__device__ __forceinline__ void scharr_pt(const float* __restrict__ p, int y, int x,
                                          int H, int W, float& G0, float& G1){
    const float* r = p + y*W + x;
    float a  = (y>0   && x>0  ) ? __ldg(r-W-1) : 0.f;
    float b  = (y>0           ) ? __ldg(r-W  ) : 0.f;
    float cc = (y>0   && x<W-1) ? __ldg(r-W+1) : 0.f;
    float d  = (         x>0  ) ? __ldg(r  -1) : 0.f;
    float e  = (         x<W-1) ? __ldg(r  +1) : 0.f;
    float f  = (y<H-1 && x>0  ) ? __ldg(r+W-1) : 0.f;
    float gg = (y<H-1         ) ? __ldg(r+W  ) : 0.f;
    float h  = (y<H-1 && x<W-1) ? __ldg(r+W+1) : 0.f;
    G0 = -3.f*a + 3.f*cc + 10.f*d + 10.f*e - 3.f*f + 3.f*h;
    G1 = -3.f*a + 10.f*b - 3.f*cc + 3.f*f  + 10.f*gg + 3.f*h;
}

// ==================== kernels ====================

__global__ void ss12_zero(){
    int i = blockIdx.x*blockDim.x + threadIdx.x;
    int stride = gridDim.x*blockDim.x;
    for (int j = i; j < NSEG*3*4*TB; j += stride) v12_th[j] = 0u;
    for (int j = i; j < NSEG*3*CB;   j += stride) v12_ch[j] = 0;
    for (int j = i; j < NSEG; j += stride)
        v12_bbox[j] = make_int4(0x7FFFFFFF, (int)0x80000000, 0x7FFFFFFF, (int)0x80000000);
    if (i < 12){ v12_mink[i] = 0xFFFFFFFFu; v12_maxk[i] = 0u; }
    if (i == 0) v12_w64 = 1;
}

// int64-vs-int32 sniff on reg_lab (labels < 5000 -> int64 high words all zero).
__global__ void ss12_dtype(const int* __restrict__ r32){
    int i = blockIdx.x*blockDim.x + threadIdx.x;    // 4096 threads
    if (r32[2*i+1] != 0) v12_w64 = 0;               // benign same-value race
}

// rotate img by +45 into 1449^2 canvas (nearest, round-half-even, zero fill).
__global__ void ss12_rot45(const float* __restrict__ img){
    int x = blockIdx.x*blockDim.x + threadIdx.x;
    int y = blockIdx.y;
    if (x >= R1) return;
    float dx = __fsub_rn((float)x, 724.0f);
    float dy = __fsub_rn((float)y, 724.0f);
    float t1 = __fmul_rn(C45f, dx);
    float t2 = __fmul_rn(C45f, dy);
    float sx = __fadd_rn(__fsub_rn(t1, t2), 511.5f);
    float sy = __fadd_rn(__fadd_rn(t1, t2), 511.5f);
    bool valid = (sx >= -0.5f) & (sx <= 1023.5f) & (sy >= -0.5f) & (sy <= 1023.5f);
    int ix = min(max((int)rintf(sx), 0), HWDIM-1);
    int iy = min(max((int)rintf(sy), 0), HWDIM-1);
    int src = iy*HWDIM + ix;
    int p = y*R1 + x;
    #pragma unroll
    for (int c = 0; c < 3; c++)
        v12_rotimg[c*NR1 + p] = valid ? __ldg(img + c*NPIX + src) : 0.f;
}

// Fused gradients pass:
//  - base Scharr of img -> v12_gbase
//  - Scharr(rotimg) evaluated AT the back-rotated(-45)+cropped sample point -> v12_grot
//    (bitwise identical to materialize-then-gather: gather of a pure function = function at
//     the gathered point)
//  - warp+atomic min/max of all 12 raw-gradient planes.
__global__ void ss12_grads(const float* __restrict__ img){
    int p = blockIdx.x*blockDim.x + threadIdx.x;    // exactly NPIX
    int x = p & (HWDIM-1), y = p >> 10;
    float dx = __fsub_rn((float)(x + CROP), 1024.5f);
    float dy = __fsub_rn((float)(y + CROP), 1024.5f);
    float t1 = __fmul_rn(C45f, dx);
    float t2 = __fmul_rn(C45f, dy);
    // angle=-45: c=+C45, s=-C45:  sx = c*dx - s*dy + 724 ; sy = s*dx + c*dy + 724
    float sx = __fadd_rn(__fadd_rn(t1, t2), 724.0f);
    float sy = __fadd_rn(__fsub_rn(t2, t1), 724.0f);
    bool valid = (sx >= -0.5f) & (sx <= 1448.5f) & (sy >= -0.5f) & (sy <= 1448.5f);
    int ix = min(max((int)rintf(sx), 0), R1-1);
    int iy = min(max((int)rintf(sy), 0), R1-1);

    float mn[12], mx[12];
    #pragma unroll
    for (int c = 0; c < 3; c++){
        float G0, G1;
        scharr_pt(img + c*NPIX, y, x, HWDIM, HWDIM, G0, G1);
        v12_gbase[c*NPIX + p] = make_float2(G0, G1);
        mn[2*c+0] = mx[2*c+0] = G0;
        mn[2*c+1] = mx[2*c+1] = G1;

        float R0 = 0.f, R1v = 0.f;
        if (valid) scharr_pt(v12_rotimg + c*NR1, iy, ix, R1, R1, R0, R1v);
        v12_grot[c*NPIX + p] = make_float2(R0, R1v);
        mn[6+2*c+0] = mx[6+2*c+0] = R0;
        mn[6+2*c+1] = mx[6+2*c+1] = R1v;
    }
    #pragma unroll
    for (int i = 0; i < 12; i++){
        #pragma unroll
        for (int off = 16; off; off >>= 1){
            mn[i] = fminf(mn[i], __shfl_xor_sync(0xFFFFFFFFu, mn[i], off));
            mx[i] = fmaxf(mx[i], __shfl_xor_sync(0xFFFFFFFFu, mx[i], off));
        }
    }
    if ((threadIdx.x & 31) == 0){
        #pragma unroll
        for (int i = 0; i < 12; i++){
            atomicMin(&v12_mink[i], fkey(mn[i]));
            atomicMax(&v12_maxk[i], fkey(mx[i]));
        }
    }
}

// normalization constants + the constant bin of value 0.0 per channel.
// Channel order within each c: [g0+, g1+, g0-, g1-, r0+, r1+, r0-, r1-].
__global__ void ss12_norm(){
    int k = threadIdx.x;
    if (k >= 24) return;
    int c = k >> 3, ch = k & 7;
    int gd = ch & 1;
    bool isrot = ch >= 4;
    bool ispos = ((ch >> 1) & 1) == 0;
    int m = (isrot ? 6 : 0) + c*2 + gd;
    float gmin = unfkey(v12_mink[m]);
    float gmax = unfkey(v12_maxk[m]);
    float hmin, hmax;
    if (ispos){ hmin = fmaxf(gmin, 0.f); hmax = fmaxf(gmax, 0.f); }
    else      { hmin = fminf(gmin, 0.f); hmax = fminf(gmax, 0.f); }
    float rcp = __frcp_rn(__fsub_rn(hmax, hmin));   // XLA's hoisted 1/(hmax-hmin)
    v12_nmin[k] = hmin;
    v12_nrcp[k] = rcp;
    v12_tbin[k] = binq(0.0f, hmin, rcp);
}

// per-pixel stats.
// Bbox: conditional REDs — read current bounds (L2) and only issue the atomic when it would
// improve. Sound because bounds move monotonically: a stale read is always >= current for
// mins (<= for maxes), so a skip implies the bound is already at least as good.
// Texture: data bins only (16-bit packed even/odd channels, same-word merges); the constant
// bin(0) mass per channel is reconstructed exactly later as size - sum(data bins).
__global__ void ss12_hist(const float* __restrict__ img, const void* __restrict__ reg){
    __shared__ float s_hmin[24], s_hr[24];
    if (threadIdx.x < 24){
        s_hmin[threadIdx.x] = v12_nmin[threadIdx.x];
        s_hr[threadIdx.x]   = v12_nrcp[threadIdx.x];
    }
    __syncthreads();

    int p = blockIdx.x*blockDim.x + threadIdx.x;    // exactly NPIX
    int x = p & (HWDIM-1), y = p >> 10;
    int s;
    if (v12_w64) s = (int)__ldg((const long long*)reg + p);
    else         s = __ldg((const int*)reg + p);
    if ((unsigned)s >= (unsigned)NSEG) return;      // defensive

    float v[3]; float2 gb[3], gr[3];
    #pragma unroll
    for (int c = 0; c < 3; c++){
        v[c]  = __ldg(img + c*NPIX + p);
        gb[c] = __ldg(&v12_gbase[c*NPIX + p]);
        gr[c] = __ldg(&v12_grot [c*NPIX + p]);
    }

    int4 bb = __ldcg(&v12_bbox[s]);                 // L2-fresh snapshot of bounds
    if (x < bb.x) atomicMin(&v12_bbox[s].x, x);
    if (x > bb.y) atomicMax(&v12_bbox[s].y, x);
    if (y < bb.z) atomicMin(&v12_bbox[s].z, y);
    if (y > bb.w) atomicMax(&v12_bbox[s].w, y);

    #pragma unroll
    for (int c = 0; c < 3; c++){
        int qc = (int)(v[c] * 24.0f);
        atomicAdd(&v12_ch[(s*3+c)*CB + qc], 1);

        unsigned bw = (unsigned)(s*3+c)*40u;        // 4 pairs * 10 bins per (s,c)
        #pragma unroll
        for (int gi = 0; gi < 2; gi++){             // gi=0: base grads (ch 0..3), gi=1: rot (4..7)
            float A = gi ? gr[c].x : gb[c].x;
            float B = gi ? gr[c].y : gb[c].y;
            int off = gi*4;
            int wA = -1, wB = -1;
            if (A != 0.f){
                int ch = off + ((A > 0.f) ? 0 : 2);
                int k = c*8 + ch;
                wA = (int)bw + (ch>>1)*10 + binq(A, s_hmin[k], s_hr[k]);
            }
            if (B != 0.f){
                int ch = off + ((B > 0.f) ? 1 : 3);
                int k = c*8 + ch;
                wB = (int)bw + (ch>>1)*10 + binq(B, s_hmin[k], s_hr[k]);
            }
            if (wA >= 0 && wA == wB) atomicAdd(&v12_th[wA], 0x10001u);
            else {
                if (wA >= 0) atomicAdd(&v12_th[wA], 1u);
                if (wB >= 0) atomicAdd(&v12_th[wB], 0x10000u);
            }
        }
    }
}

// region sizes derived exactly from color counts (each pixel adds exactly 3 color counts).
__global__ void ss12_sizes(){
    int s = blockIdx.x*blockDim.x + threadIdx.x;
    if (s >= NSEG) return;
    int t = 0;
    #pragma unroll 5
    for (int j = 0; j < 3*CB; j++) t += __ldg(v12_ch + s*3*CB + j);
    v12_sz[s] = t / 3;
}

// add the deferred constant-bin mass per (s,c,pair,half): missing = size - sum(data bins).
// Exclusive ownership per thread -> plain RMW, no atomics.
__global__ void ss12_corr(){
    int t = blockIdx.x*blockDim.x + threadIdx.x;    // NSEG*12 threads
    if (t >= NSEG*12) return;
    int s = t / 12, cp = t % 12;
    int c = cp >> 2, pr = cp & 3;
    unsigned base = (unsigned)(s*3+c)*40u + pr*10;
    unsigned w[TB];
    int sum0 = 0, sum1 = 0;
    #pragma unroll
    for (int b = 0; b < TB; b++){
        w[b] = v12_th[base + b];
        sum0 += (int)(w[b] & 0xFFFFu);
        sum1 += (int)(w[b] >> 16);
    }
    int size = v12_sz[s];
    int t0 = v12_tbin[c*8 + pr*2 + 0];
    int t1 = v12_tbin[c*8 + pr*2 + 1];
    w[t0] += (unsigned)(size - sum0);
    w[t1] += (unsigned)(size - sum1) << 16;
    v12_th[base + t0] = w[t0];
    if (t1 != t0) v12_th[base + t1] = w[t1];
}

// outputs: xywh (5000,4) | sizes (5000) | color (5000,3,25) | tex (5000,3,8,10)
// normalizations: count * frcp_rn(denom), matching XLA's divide->reciprocal rewrite.
__global__ void ss12_out(float* __restrict__ out, int out_size){
    int i = blockIdx.x*blockDim.x + threadIdx.x;
    if (i >= OUT_TOTAL || i >= out_size) return;
    if (i < 20000){
        int s = i >> 2, j = i & 3;
        int4 bb = v12_bbox[s];
        int v;
        if      (j == 0) v = bb.x;
        else if (j == 1) v = bb.z;
        else if (j == 2) v = bb.y - bb.x;
        else             v = bb.w - bb.z;
        out[i] = (float)v;
    } else if (i < 25000){
        out[i] = (float)v12_sz[i - 20000];
    } else if (i < 400000){
        int j = i - 25000;
        int s = j / 75;
        float rcp = __frcp_rn(__fmul_rn(3.0f, (float)v12_sz[s]));
        out[i] = __fmul_rn((float)v12_ch[j], rcp);
    } else {
        int j = i - 400000;
        int s = j / 240;
        int r = j % 240;
        int c = r / 80;  r %= 80;
        int ch = r / 10; int b = r % 10;
        unsigned w = v12_th[(unsigned)(s*3+c)*40u + (ch>>1)*10 + b];
        int cnt = (int)((w >> (16*(ch & 1))) & 0xFFFFu);
        float rcp = __frcp_rn(__fmul_rn(24.0f, (float)v12_sz[s]));
        out[i] = __fmul_rn((float)cnt, rcp);
    }
}

extern "C" void kernel_launch(void* const* d_in, const int* in_sizes, int n_in,
                              void* d_out, int out_size){
    const float* img = (const float*)d_in[0];
    const void*  reg = d_in[1];
    float* out = (float*)d_out;

    dim3 canvas_grid((R1 + 255)/256, R1);

    ss12_zero<<<2048, 256>>>();
    ss12_dtype<<<16, 256>>>((const int*)reg);
    ss12_rot45<<<canvas_grid, 256>>>(img);
    ss12_grads<<<NPIX/256, 256>>>(img);
    ss12_norm<<<1, 32>>>();
    ss12_hist<<<NPIX/256, 256>>>(img, reg);
    ss12_sizes<<<(NSEG + 255)/256, 256>>>();
    ss12_corr<<<(NSEG*12 + 255)/256, 256>>>();
    ss12_out<<<(OUT_TOTAL + 255)/256, 256>>>(out, out_size);
}

// round 14
// speedup vs baseline: 1.3867x; 1.3867x over previous
#include <cuda_runtime.h>
#include <cstdint>

#define HWDIM 1024
#define NPIX  (HWDIM*HWDIM)
#define NSEG  5000
#define R1    1449
#define NR1   (R1*R1)
#define CROP  211
#define CB    25
#define TB    10
#define OUT_TOTAL 1600000

#define C45f 0.70710678118654752440f
#define TW   48          // staged tile max extent (true max 45)

// -------- device scratch (static; no runtime allocation) --------
__device__ float    v13_rotimg[3*NR1];      // +45-rotated image, 1449^2 per channel
__device__ float2   v13_gradrot[3*NR1];     // Scharr of rotated canvas, (G0,G1) per c (planes)
__device__ float2   v13_gbase[3*NPIX];      // Scharr of original img
__device__ float2   v13_grot[3*NPIX];       // back-rotated(-45)+cropped scharr
__device__ unsigned v13_mink[12], v13_maxk[12];
__device__ float    v13_nmin[24], v13_nrcp[24];
__device__ int      v13_tbin[24];           // bin of value 0.0 per deriv channel
__device__ int4     v13_bbox[NSEG];         // {xmin, xmax, ymin, ymax}
__device__ int      v13_sz[NSEG];
__device__ int      v13_ch[NSEG*3*CB];
__device__ unsigned v13_th[NSEG*3*4*TB];    // [s][c][pair(4)][bin(10)]; lo16 even ch, hi16 odd
__device__ int      v13_w64;

// -------- helpers --------
__device__ __forceinline__ unsigned fkey(float f){
    unsigned u = __float_as_uint(f);
    return (u & 0x80000000u) ? ~u : (u | 0x80000000u);
}
__device__ __forceinline__ float unfkey(unsigned k){
    unsigned u = (k & 0x80000000u) ? (k ^ 0x80000000u) : ~k;
    return __uint_as_float(u);
}
__device__ __forceinline__ int binq(float val, float hmin, float rcp){
    float d = __fmul_rn(__fsub_rn(val, hmin), rcp);
    int q = (int)__fmul_rn(d, 9.0f);
    return min(max(q, 0), TB-1);
}
__device__ __forceinline__ void scharr_pt(const float* __restrict__ p, int y, int x,
                                          int H, int W, float& G0, float& G1){
    const float* r = p + y*W + x;
    float a  = (y>0   && x>0  ) ? __ldg(r-W-1) : 0.f;
    float b  = (y>0           ) ? __ldg(r-W  ) : 0.f;
    float cc = (y>0   && x<W-1) ? __ldg(r-W+1) : 0.f;
    float d  = (         x>0  ) ? __ldg(r  -1) : 0.f;
    float e  = (         x<W-1) ? __ldg(r  +1) : 0.f;
    float f  = (y<H-1 && x>0  ) ? __ldg(r+W-1) : 0.f;
    float gg = (y<H-1         ) ? __ldg(r+W  ) : 0.f;
    float h  = (y<H-1 && x<W-1) ? __ldg(r+W+1) : 0.f;
    G0 = -3.f*a + 3.f*cc + 10.f*d + 10.f*e - 3.f*f + 3.f*h;
    G1 = -3.f*a + 10.f*b - 3.f*cc + 3.f*f  + 10.f*gg + 3.f*h;
}

// ==================== kernels ====================

__global__ void ss13_zero(){
    int i = blockIdx.x*blockDim.x + threadIdx.x;
    int stride = gridDim.x*blockDim.x;
    for (int j = i; j < NSEG*3*4*TB; j += stride) v13_th[j] = 0u;
    for (int j = i; j < NSEG*3*CB;   j += stride) v13_ch[j] = 0;
    for (int j = i; j < NSEG; j += stride)
        v13_bbox[j] = make_int4(0x7FFFFFFF, (int)0x80000000, 0x7FFFFFFF, (int)0x80000000);
    if (i < 12){ v13_mink[i] = 0xFFFFFFFFu; v13_maxk[i] = 0u; }
    if (i == 0) v13_w64 = 1;
}

__global__ void ss13_dtype(const int* __restrict__ r32){
    int i = blockIdx.x*blockDim.x + threadIdx.x;    // 4096 threads
    if (r32[2*i+1] != 0) v13_w64 = 0;               // benign same-value race
}

// rotate img by +45 into 1449^2 canvas (nearest, round-half-even, zero fill).
__global__ void ss13_rot45(const float* __restrict__ img){
    int x = blockIdx.x*blockDim.x + threadIdx.x;
    int y = blockIdx.y;
    if (x >= R1) return;
    float dx = __fsub_rn((float)x, 724.0f);
    float dy = __fsub_rn((float)y, 724.0f);
    float t1 = __fmul_rn(C45f, dx);
    float t2 = __fmul_rn(C45f, dy);
    float sx = __fadd_rn(__fsub_rn(t1, t2), 511.5f);
    float sy = __fadd_rn(__fadd_rn(t1, t2), 511.5f);
    bool valid = (sx >= -0.5f) & (sx <= 1023.5f) & (sy >= -0.5f) & (sy <= 1023.5f);
    int ix = min(max((int)rintf(sx), 0), HWDIM-1);
    int iy = min(max((int)rintf(sy), 0), HWDIM-1);
    int src = iy*HWDIM + ix;
    int p = y*R1 + x;
    #pragma unroll
    for (int c = 0; c < 3; c++)
        v13_rotimg[c*NR1 + p] = valid ? __ldg(img + c*NPIX + src) : 0.f;
}

// Scharr over the rotated canvas (coalesced), materialized as float2 planes.
__global__ void ss13_scharr_rot(){
    int x = blockIdx.x*blockDim.x + threadIdx.x;
    int y = blockIdx.y;
    if (x >= R1) return;
    int p = y*R1 + x;
    #pragma unroll
    for (int c = 0; c < 3; c++){
        float G0, G1;
        scharr_pt(v13_rotimg + c*NR1, y, x, R1, R1, G0, G1);
        v13_gradrot[c*NR1 + p] = make_float2(G0, G1);
    }
}

// base Scharr of img (coalesced) + min/max of base planes (keys 0..5).
__global__ void ss13_scharr_base(const float* __restrict__ img){
    int p = blockIdx.x*blockDim.x + threadIdx.x;    // exactly NPIX
    int x = p & (HWDIM-1), y = p >> 10;
    float mn[6], mx[6];
    #pragma unroll
    for (int c = 0; c < 3; c++){
        float G0, G1;
        scharr_pt(img + c*NPIX, y, x, HWDIM, HWDIM, G0, G1);
        v13_gbase[c*NPIX + p] = make_float2(G0, G1);
        mn[2*c+0] = mx[2*c+0] = G0;
        mn[2*c+1] = mx[2*c+1] = G1;
    }
    #pragma unroll
    for (int i = 0; i < 6; i++){
        #pragma unroll
        for (int off = 16; off; off >>= 1){
            mn[i] = fminf(mn[i], __shfl_xor_sync(0xFFFFFFFFu, mn[i], off));
            mx[i] = fmaxf(mx[i], __shfl_xor_sync(0xFFFFFFFFu, mx[i], off));
        }
    }
    if ((threadIdx.x & 31) == 0){
        #pragma unroll
        for (int i = 0; i < 6; i++){
            atomicMin(&v13_mink[i], fkey(mn[i]));
            atomicMax(&v13_maxk[i], fkey(mx[i]));
        }
    }
}

// SMEM-TILED back-rotation gather.
// Each block handles a 32x32 output tile (256 threads, 4 px each). The exact source bbox
// (from the clamped per-pixel coords, block-reduced) is staged into smem with coalesced
// row loads; gathers then hit smem. Values are bit-identical to direct __ldg gathers.
// Also reduces min/max of the 6 rotated planes (keys 6..11).
__global__ void __launch_bounds__(256) ss13_backrot(){
    __shared__ float2 s_tile[TW*TW];
    __shared__ int s_bx0, s_bx1, s_by0, s_by1;
    int tid = threadIdx.x;
    int tileX = blockIdx.x << 5, tileY = blockIdx.y << 5;
    if (tid == 0){ s_bx0 = 1<<30; s_by0 = 1<<30; s_bx1 = -(1<<30); s_by1 = -(1<<30); }
    __syncthreads();

    int ixs[4], iys[4]; bool vals[4];
    int lx0 = 1<<30, ly0 = 1<<30, lx1 = -(1<<30), ly1 = -(1<<30);
    #pragma unroll
    for (int k = 0; k < 4; k++){
        int j = tid + (k << 8);
        int x = tileX + (j & 31), y = tileY + (j >> 5);
        float dx = __fsub_rn((float)(x + CROP), 1024.5f);
        float dy = __fsub_rn((float)(y + CROP), 1024.5f);
        float t1 = __fmul_rn(C45f, dx);
        float t2 = __fmul_rn(C45f, dy);
        float sx = __fadd_rn(__fadd_rn(t1, t2), 724.0f);
        float sy = __fadd_rn(__fsub_rn(t2, t1), 724.0f);
        bool valid = (sx >= -0.5f) & (sx <= 1448.5f) & (sy >= -0.5f) & (sy <= 1448.5f);
        int ix = min(max((int)rintf(sx), 0), R1-1);
        int iy = min(max((int)rintf(sy), 0), R1-1);
        ixs[k] = ix; iys[k] = iy; vals[k] = valid;
        lx0 = min(lx0, ix); lx1 = max(lx1, ix);
        ly0 = min(ly0, iy); ly1 = max(ly1, iy);
    }
    atomicMin(&s_bx0, lx0); atomicMax(&s_bx1, lx1);
    atomicMin(&s_by0, ly0); atomicMax(&s_by1, ly1);
    __syncthreads();
    int bx = s_bx0, by = s_by0;
    int w = s_bx1 - bx + 1, h = s_by1 - by + 1;
    bool big = (w > TW) | (h > TW);   // mathematically impossible; safety fallback

    float mn[6], mx[6];
    #pragma unroll
    for (int c = 0; c < 3; c++){
        float2 g[4];
        if (!big){
            __syncthreads();
            const float2* src = v13_gradrot + c*NR1;
            for (int t = tid; t < h*TW; t += 256){
                int ry = t / TW, rx = t - ry*TW;
                if (rx < w) s_tile[t] = __ldg(&src[(by+ry)*R1 + bx + rx]);
            }
            __syncthreads();
            #pragma unroll
            for (int k = 0; k < 4; k++)
                g[k] = vals[k] ? s_tile[(iys[k]-by)*TW + (ixs[k]-bx)] : make_float2(0.f,0.f);
        } else {
            #pragma unroll
            for (int k = 0; k < 4; k++)
                g[k] = vals[k] ? __ldg(&v13_gradrot[c*NR1 + iys[k]*R1 + ixs[k]])
                               : make_float2(0.f,0.f);
        }
        float m0 = g[0].x, M0 = g[0].x, m1 = g[0].y, M1 = g[0].y;
        #pragma unroll
        for (int k = 0; k < 4; k++){
            int j = tid + (k << 8);
            int x = tileX + (j & 31), y = tileY + (j >> 5);
            v13_grot[c*NPIX + y*HWDIM + x] = g[k];
            m0 = fminf(m0, g[k].x); M0 = fmaxf(M0, g[k].x);
            m1 = fminf(m1, g[k].y); M1 = fmaxf(M1, g[k].y);
        }
        mn[2*c+0] = m0; mx[2*c+0] = M0;
        mn[2*c+1] = m1; mx[2*c+1] = M1;
    }
    #pragma unroll
    for (int i = 0; i < 6; i++){
        #pragma unroll
        for (int off = 16; off; off >>= 1){
            mn[i] = fminf(mn[i], __shfl_xor_sync(0xFFFFFFFFu, mn[i], off));
            mx[i] = fmaxf(mx[i], __shfl_xor_sync(0xFFFFFFFFu, mx[i], off));
        }
    }
    if ((tid & 31) == 0){
        #pragma unroll
        for (int i = 0; i < 6; i++){
            atomicMin(&v13_mink[6+i], fkey(mn[i]));
            atomicMax(&v13_maxk[6+i], fkey(mx[i]));
        }
    }
}

// normalization constants + constant bin of value 0.0 per channel.
// Channel order within each c: [g0+, g1+, g0-, g1-, r0+, r1+, r0-, r1-].
__global__ void ss13_norm(){
    int k = threadIdx.x;
    if (k >= 24) return;
    int c = k >> 3, ch = k & 7;
    int gd = ch & 1;
    bool isrot = ch >= 4;
    bool ispos = ((ch >> 1) & 1) == 0;
    int m = (isrot ? 6 : 0) + c*2 + gd;
    float gmin = unfkey(v13_mink[m]);
    float gmax = unfkey(v13_maxk[m]);
    float hmin, hmax;
    if (ispos){ hmin = fmaxf(gmin, 0.f); hmax = fmaxf(gmax, 0.f); }
    else      { hmin = fminf(gmin, 0.f); hmax = fminf(gmax, 0.f); }
    float rcp = __frcp_rn(__fsub_rn(hmax, hmin));   // XLA's hoisted 1/(hmax-hmin)
    v13_nmin[k] = hmin;
    v13_nrcp[k] = rcp;
    v13_tbin[k] = binq(0.0f, hmin, rcp);
}

// per-pixel stats. Conditional bbox REDs (monotonic bounds -> stale-read skip is sound).
// Texture: data bins only, 16-bit packed; constant-bin mass reconstructed exactly later.
__global__ void ss13_hist(const float* __restrict__ img, const void* __restrict__ reg){
    __shared__ float s_hmin[24], s_hr[24];
    if (threadIdx.x < 24){
        s_hmin[threadIdx.x] = v13_nmin[threadIdx.x];
        s_hr[threadIdx.x]   = v13_nrcp[threadIdx.x];
    }
    __syncthreads();

    int p = blockIdx.x*blockDim.x + threadIdx.x;    // exactly NPIX
    int x = p & (HWDIM-1), y = p >> 10;
    int s;
    if (v13_w64) s = (int)__ldg((const long long*)reg + p);
    else         s = __ldg((const int*)reg + p);
    if ((unsigned)s >= (unsigned)NSEG) return;      // defensive

    float v[3]; float2 gb[3], gr[3];
    #pragma unroll
    for (int c = 0; c < 3; c++){
        v[c]  = __ldg(img + c*NPIX + p);
        gb[c] = __ldg(&v13_gbase[c*NPIX + p]);
        gr[c] = __ldg(&v13_grot [c*NPIX + p]);
    }

    int4 bb = __ldcg(&v13_bbox[s]);
    if (x < bb.x) atomicMin(&v13_bbox[s].x, x);
    if (x > bb.y) atomicMax(&v13_bbox[s].y, x);
    if (y < bb.z) atomicMin(&v13_bbox[s].z, y);
    if (y > bb.w) atomicMax(&v13_bbox[s].w, y);

    #pragma unroll
    for (int c = 0; c < 3; c++){
        int qc = (int)(v[c] * 24.0f);
        atomicAdd(&v13_ch[(s*3+c)*CB + qc], 1);

        unsigned bw = (unsigned)(s*3+c)*40u;
        #pragma unroll
        for (int gi = 0; gi < 2; gi++){
            float A = gi ? gr[c].x : gb[c].x;
            float B = gi ? gr[c].y : gb[c].y;
            int off = gi*4;
            int wA = -1, wB = -1;
            if (A != 0.f){
                int ch = off + ((A > 0.f) ? 0 : 2);
                int k = c*8 + ch;
                wA = (int)bw + (ch>>1)*10 + binq(A, s_hmin[k], s_hr[k]);
            }
            if (B != 0.f){
                int ch = off + ((B > 0.f) ? 1 : 3);
                int k = c*8 + ch;
                wB = (int)bw + (ch>>1)*10 + binq(B, s_hmin[k], s_hr[k]);
            }
            if (wA >= 0 && wA == wB) atomicAdd(&v13_th[wA], 0x10001u);
            else {
                if (wA >= 0) atomicAdd(&v13_th[wA], 1u);
                if (wB >= 0) atomicAdd(&v13_th[wB], 0x10000u);
            }
        }
    }
}

// sizes from color counts (each pixel contributes exactly 3 color counts).
__global__ void ss13_sizes(){
    int s = blockIdx.x*blockDim.x + threadIdx.x;
    if (s >= NSEG) return;
    int t = 0;
    #pragma unroll 5
    for (int j = 0; j < 3*CB; j++) t += __ldg(v13_ch + s*3*CB + j);
    v13_sz[s] = t / 3;
}

// deferred constant-bin mass: per (s,c,pair,half) missing = size - sum(data bins).
__global__ void ss13_corr(){
    int t = blockIdx.x*blockDim.x + threadIdx.x;    // NSEG*12 threads
    if (t >= NSEG*12) return;
    int s = t / 12, cp = t % 12;
    int c = cp >> 2, pr = cp & 3;
    unsigned base = (unsigned)(s*3+c)*40u + pr*10;
    unsigned w[TB];
    int sum0 = 0, sum1 = 0;
    #pragma unroll
    for (int b = 0; b < TB; b++){
        w[b] = v13_th[base + b];
        sum0 += (int)(w[b] & 0xFFFFu);
        sum1 += (int)(w[b] >> 16);
    }
    int size = v13_sz[s];
    int t0 = v13_tbin[c*8 + pr*2 + 0];
    int t1 = v13_tbin[c*8 + pr*2 + 1];
    w[t0] += (unsigned)(size - sum0);
    w[t1] += (unsigned)(size - sum1) << 16;
    v13_th[base + t0] = w[t0];
    if (t1 != t0) v13_th[base + t1] = w[t1];
}

// outputs: xywh (5000,4) | sizes (5000) | color (5000,3,25) | tex (5000,3,8,10)
__global__ void ss13_out(float* __restrict__ out, int out_size){
    int i = blockIdx.x*blockDim.x + threadIdx.x;
    if (i >= OUT_TOTAL || i >= out_size) return;
    if (i < 20000){
        int s = i >> 2, j = i & 3;
        int4 bb = v13_bbox[s];
        int v;
        if      (j == 0) v = bb.x;
        else if (j == 1) v = bb.z;
        else if (j == 2) v = bb.y - bb.x;
        else             v = bb.w - bb.z;
        out[i] = (float)v;
    } else if (i < 25000){
        out[i] = (float)v13_sz[i - 20000];
    } else if (i < 400000){
        int j = i - 25000;
        int s = j / 75;
        float rcp = __frcp_rn(__fmul_rn(3.0f, (float)v13_sz[s]));
        out[i] = __fmul_rn((float)v13_ch[j], rcp);
    } else {
        int j = i - 400000;
        int s = j / 240;
        int r = j % 240;
        int c = r / 80;  r %= 80;
        int ch = r / 10; int b = r % 10;
        unsigned w = v13_th[(unsigned)(s*3+c)*40u + (ch>>1)*10 + b];
        int cnt = (int)((w >> (16*(ch & 1))) & 0xFFFFu);
        float rcp = __frcp_rn(__fmul_rn(24.0f, (float)v13_sz[s]));
        out[i] = __fmul_rn((float)cnt, rcp);
    }
}

extern "C" void kernel_launch(void* const* d_in, const int* in_sizes, int n_in,
                              void* d_out, int out_size){
    const float* img = (const float*)d_in[0];
    const void*  reg = d_in[1];
    float* out = (float*)d_out;

    dim3 canvas_grid((R1 + 255)/256, R1);

    ss13_zero<<<2048, 256>>>();
    ss13_dtype<<<16, 256>>>((const int*)reg);
    ss13_rot45<<<canvas_grid, 256>>>(img);
    ss13_scharr_rot<<<canvas_grid, 256>>>();
    ss13_scharr_base<<<NPIX/256, 256>>>(img);
    ss13_backrot<<<dim3(32, 32), 256>>>();
    ss13_norm<<<1, 32>>>();
    ss13_hist<<<NPIX/256, 256>>>(img, reg);
    ss13_sizes<<<(NSEG + 255)/256, 256>>>();
    ss13_corr<<<(NSEG*12 + 255)/256, 256>>>();
    ss13_out<<<(OUT_TOTAL + 255)/256, 256>>>(out, out_size);
}